// round 4
// baseline (speedup 1.0000x reference)
#include <cuda_runtime.h>
#include <cuda_bf16.h>
#include <cstdint>

#define BB 2
#define CIN 128
#define COUT 64
#define KK 64
#define HWD 16384          // 128*128
#define NPIX (BB*HWD)      // 32768
#define GPX 128            // pixels per gemm block
#define NGB (NPIX/GPX)     // 256 gemm blocks
#define NCH 8              // pixel chunks for sums

// ---------------- scratch (device globals; no allocation) ----------------
__device__ float g_xt[BB*COUT*HWD];        // xt in [b][o][p] layout (8MB)
__device__ float g_sumsp[BB*KK*COUT*NCH];  // partial bin sums [b][k][o][ch]
__device__ float g_cntp[BB*KK*NCH];        // partial counts   [b][k][ch]
__device__ float g_A[COUT*COUT];           // inv(cov)
__device__ float g_adjmT[BB*KK*COUT];      // adj @ means, TRANSPOSED [b][o][i]
__device__ float g_psum[8*COUT];           // BN partial sums  [(b*4+cx)][o]
__device__ float g_psq[8*COUT];            // BN partial sumsq

// ---------------- kernel 1: GEMM xt = x*Wft  (+ inverse in extra block) ----------------
__global__ void __launch_bounds__(256) k_gemm(const float* __restrict__ x,
                                              const float* __restrict__ Wft,
                                              const float* __restrict__ Wm) {
    __shared__ float sbuf[8576];    // gemm: sX[4096]+sW[2048]; GJ: aug 64*133=8512
    __shared__ float prow[128];
    __shared__ float fcol[64];
    const int tid = threadIdx.x;

    if (blockIdx.x == NGB) {
        // ======== cov = Wm Wm^T, Gauss-Jordan inverse (SPD, no pivot) ========
        for (int i = tid; i < 64*64; i += 256) { int r = i >> 6, c = i & 63; sbuf[r*65+c] = Wm[i]; }
        __syncthreads();
        const int i0 = tid & 63, jg = tid >> 6;   // row i0, j-group of 16
        float cv[16];
        #pragma unroll
        for (int jj = 0; jj < 16; jj++) {
            int j = jg*16 + jj;
            float sum = 0.f;
            #pragma unroll 8
            for (int c = 0; c < 64; c++) sum += sbuf[i0*65+c] * sbuf[j*65+c];
            cv[jj] = sum;
        }
        __syncthreads();
        #pragma unroll
        for (int jj = 0; jj < 16; jj++) sbuf[i0*133 + jg*16 + jj] = cv[jj];
        for (int t = tid; t < 64*64; t += 256) { int r = t >> 6, c = t & 63; sbuf[r*133 + 64 + c] = (r == c) ? 1.f : 0.f; }
        const int r = tid & 63, part = tid >> 6;   // row r, 32-col slice
        for (int c = 0; c < 64; c++) {
            __syncthreads();
            if (tid < 128)       prow[tid]     = sbuf[c*133 + tid] * (1.0f / sbuf[c*133 + c]);
            else if (tid < 192)  fcol[tid-128] = sbuf[(tid-128)*133 + c];
            __syncthreads();
            float f = fcol[r];
            if (r == c) {
                for (int j = part*32; j < part*32 + 32; j++) sbuf[r*133 + j] = prow[j];
            } else {
                for (int j = part*32; j < part*32 + 32; j++) sbuf[r*133 + j] -= f * prow[j];
            }
        }
        __syncthreads();
        for (int t = tid; t < 64*64; t += 256) { int rr = t >> 6, cc = t & 63; g_A[t] = sbuf[rr*133 + 64 + cc]; }
        return;
    }

    // ======== GEMM: 128 px x 64 outs per block; thread tile 4px x 8outs ========
    float4* sX4 = reinterpret_cast<float4*>(sbuf);          // 32 c x 32 quads
    float4* sW4 = reinterpret_cast<float4*>(sbuf + 4096);   // 32 c x 16 f4
    const int GP = blockIdx.x * GPX;
    const int b  = GP >> 14;
    const int P0 = GP & (HWD - 1);
    const int quad = tid & 31;        // pixel quad: px = quad*4..quad*4+3
    const int og   = tid >> 5;        // out group: o = og*8..og*8+7

    float a[4][8];
    #pragma unroll
    for (int p = 0; p < 4; p++)
        #pragma unroll
        for (int o = 0; o < 8; o++) a[p][o] = 0.f;

    for (int ch = 0; ch < 4; ch++) {
        __syncthreads();
        sW4[tid]       = reinterpret_cast<const float4*>(Wft)[ch*512 + tid];
        sW4[tid + 256] = reinterpret_cast<const float4*>(Wft)[ch*512 + tid + 256];
        const float* xbase = x + ((size_t)(b*CIN + ch*32)) * HWD + P0;
        #pragma unroll
        for (int t = 0; t < 4; t++) {
            int q = tid + t*256;
            int r = q >> 5, c4 = q & 31;
            sX4[r*32 + c4] = *reinterpret_cast<const float4*>(xbase + (size_t)r * HWD + c4*4);
        }
        __syncthreads();

        #pragma unroll 4
        for (int cc = 0; cc < 32; cc++) {
            float4 xv = sX4[cc*32 + quad];
            float4 w0 = sW4[cc*16 + og*2];
            float4 w1 = sW4[cc*16 + og*2 + 1];
            const float xs[4] = {xv.x, xv.y, xv.z, xv.w};
            const float ws[8] = {w0.x, w0.y, w0.z, w0.w, w1.x, w1.y, w1.z, w1.w};
            #pragma unroll
            for (int p = 0; p < 4; p++)
                #pragma unroll
                for (int o = 0; o < 8; o++) a[p][o] += xs[p] * ws[o];
        }
    }

    float* xtb = g_xt + (size_t)b * COUT * HWD + P0 + quad*4;
    #pragma unroll
    for (int oo = 0; oo < 8; oo++) {
        int o = og*8 + oo;
        *reinterpret_cast<float4*>(xtb + (size_t)o * HWD) =
            make_float4(a[0][oo], a[1][oo], a[2][oo], a[3][oo]);
    }
}

// ---------------- kernel 2: per-bin partial sums + counts (atomic-free) ----------------
// grid (COUT+1, BB, NCH); o==COUT slice computes counts
__global__ void __launch_bounds__(128) k_sums(const int* __restrict__ idx) {
    __shared__ float sb[64*129];
    const int tid = threadIdx.x;
    const int o = blockIdx.x, b = blockIdx.y, ch = blockIdx.z;
    for (int i = tid; i < 64*129; i += 128) sb[i] = 0.f;
    __syncthreads();
    const int4* ip4 = reinterpret_cast<const int4*>(idx + b*HWD);
    if (o < COUT) {
        const float4* xt4 = reinterpret_cast<const float4*>(g_xt + (size_t)(b*COUT + o) * HWD);
        #pragma unroll
        for (int it = 0; it < 4; it++) {
            int q = ch*512 + it*128 + tid;
            float4 v = __ldg(xt4 + q);
            int4 kk = __ldg(ip4 + q);
            sb[kk.x*129 + tid] += v.x;
            sb[kk.y*129 + tid] += v.y;
            sb[kk.z*129 + tid] += v.z;
            sb[kk.w*129 + tid] += v.w;
        }
        __syncthreads();
        int k = tid >> 1, half = tid & 1;
        float s = 0.f;
        const float* row = sb + k*129 + half*64;
        #pragma unroll 8
        for (int m = 0; m < 64; m++) s += row[m];
        s += __shfl_xor_sync(0xffffffffu, s, 1);
        if (half == 0) g_sumsp[((b*64 + k)*64 + o)*NCH + ch] = s;
    } else {
        #pragma unroll
        for (int it = 0; it < 4; it++) {
            int q = ch*512 + it*128 + tid;
            int4 kk = __ldg(ip4 + q);
            sb[kk.x*129 + tid] += 1.f;
            sb[kk.y*129 + tid] += 1.f;
            sb[kk.z*129 + tid] += 1.f;
            sb[kk.w*129 + tid] += 1.f;
        }
        __syncthreads();
        int k = tid >> 1, half = tid & 1;
        float s = 0.f;
        const float* row = sb + k*129 + half*64;
        #pragma unroll 8
        for (int m = 0; m < 64; m++) s += row[m];
        s += __shfl_xor_sync(0xffffffffu, s, 1);
        if (half == 0) g_cntp[(b*64 + k)*NCH + ch] = s;
    }
}

// ---------------- kernel 3: adjacency + adj@means per (b,i) ----------------
__global__ void __launch_bounds__(256) k_adj() {
    __shared__ float sMe[64*65];    // means, padded
    __shared__ float sA[64*64];     // inv cov
    __shared__ float adjrow[64];
    __shared__ float red[256];
    const int tid = threadIdx.x;
    const int b = blockIdx.x >> 6;
    const int i = blockIdx.x & 63;

    for (int t = tid; t < 64*64; t += 256) {
        int k = t >> 6, o = t & 63;
        const float4* sp = reinterpret_cast<const float4*>(g_sumsp + (size_t)t*NCH + (size_t)b*4096*NCH);
        float4 s0 = sp[0], s1 = sp[1];
        float sum = s0.x + s0.y + s0.z + s0.w + s1.x + s1.y + s1.z + s1.w;
        const float4* cp = reinterpret_cast<const float4*>(g_cntp + (b*64 + k)*NCH);
        float4 c0 = cp[0], c1 = cp[1];
        float cnt = c0.x + c0.y + c0.z + c0.w + c1.x + c1.y + c1.z + c1.w;
        float den = cnt + (cnt == 0.f ? 1.f : 0.f);
        sMe[k*65 + o] = sum / den;
        sA[t] = g_A[t];
    }
    __syncthreads();

    const int j = tid & 63, s = tid >> 6;
    float dreg[64];
    #pragma unroll
    for (int d = 0; d < 64; d++) dreg[d] = sMe[i*65 + d] - sMe[j*65 + d];
    float q = 0.f;
    for (int c = s*16; c < s*16 + 16; c++) {
        float w = 0.f;
        const float4* ar = reinterpret_cast<const float4*>(sA + c*64);
        #pragma unroll
        for (int d4 = 0; d4 < 16; d4++) {
            float4 aa = ar[d4];
            w += aa.x*dreg[4*d4] + aa.y*dreg[4*d4+1] + aa.z*dreg[4*d4+2] + aa.w*dreg[4*d4+3];
        }
        q += dreg[c] * w;
    }
    red[tid] = q;
    __syncthreads();
    if (tid < 64) {
        float qt = red[tid] + red[64 + tid] + red[128 + tid] + red[192 + tid];
        float dist = (tid == i) ? 1e-6f : sqrtf(fmaxf(qt, 1e-12f));
        adjrow[tid] = expf(-dist);
    }
    __syncthreads();
    const int o = tid & 63;
    float part = 0.f;
    for (int jj = s*16; jj < s*16 + 16; jj++) part += adjrow[jj] * sMe[jj*65 + o];
    red[tid] = part;
    __syncthreads();
    if (tid < 64)
        g_adjmT[b*4096 + tid*64 + i] = red[tid] + red[64 + tid] + red[128 + tid] + red[192 + tid];
}

// ---------------- kernel 4: BN partial statistics (vectorized) ----------------
__global__ void __launch_bounds__(256) k_stats(const int* __restrict__ idx) {
    __shared__ float sAm[64];
    const int tid = threadIdx.x;
    const int cx = blockIdx.x, o = blockIdx.y, b = blockIdx.z;
    if (tid < 64) sAm[tid] = g_adjmT[b*4096 + o*64 + tid];
    __syncthreads();
    const float4* xt4 = reinterpret_cast<const float4*>(g_xt + (size_t)(b*COUT + o) * HWD);
    const int4*   ip4 = reinterpret_cast<const int4*>(idx + b*HWD);
    int q0 = cx * 1024 + tid;
    float s = 0.f, sq = 0.f;
    #pragma unroll
    for (int it = 0; it < 4; it++) {
        int q = q0 + it*256;
        float4 v = __ldg(xt4 + q);
        int4 kk = __ldg(ip4 + q);
        float f0 = fmaxf(v.x + sAm[kk.x], 0.f);
        float f1 = fmaxf(v.y + sAm[kk.y], 0.f);
        float f2 = fmaxf(v.z + sAm[kk.z], 0.f);
        float f3 = fmaxf(v.w + sAm[kk.w], 0.f);
        s  += f0 + f1 + f2 + f3;
        sq += f0*f0 + f1*f1 + f2*f2 + f3*f3;
    }
    #pragma unroll
    for (int off = 16; off; off >>= 1) {
        s  += __shfl_down_sync(0xffffffffu, s, off);
        sq += __shfl_down_sync(0xffffffffu, sq, off);
    }
    __shared__ float rs[8], rq[8];
    if ((tid & 31) == 0) { rs[tid >> 5] = s; rq[tid >> 5] = sq; }
    __syncthreads();
    if (tid == 0) {
        float S = 0.f, Q = 0.f;
        #pragma unroll
        for (int w = 0; w < 8; w++) { S += rs[w]; Q += rq[w]; }
        g_psum[(b*4 + cx)*COUT + o] = S;
        g_psq [(b*4 + cx)*COUT + o] = Q;
    }
}

// ---------------- kernel 5: normalize + write output (vectorized) ----------------
__global__ void __launch_bounds__(256) k_out(const int* __restrict__ idx,
                                             const float* __restrict__ gamma,
                                             const float* __restrict__ beta,
                                             float* __restrict__ out) {
    __shared__ float sAm[64];
    __shared__ float sc, shf;
    const int tid = threadIdx.x;
    const int cx = blockIdx.x, o = blockIdx.y, b = blockIdx.z;
    if (tid < 64) sAm[tid] = g_adjmT[b*4096 + o*64 + tid];
    if (tid == 0) {
        float S = 0.f, Q = 0.f;
        #pragma unroll
        for (int i = 0; i < 8; i++) { S += g_psum[i*COUT + o]; Q += g_psq[i*COUT + o]; }
        const float invN = 1.0f / (float)NPIX;
        float mean = S * invN;
        float var  = Q * invN - mean * mean;
        float inv  = 1.0f / sqrtf(var + 1e-5f);
        float g = __ldg(gamma + o), be = __ldg(beta + o);
        sc  = g * inv;
        shf = be - mean * g * inv;
    }
    __syncthreads();
    const float4* xt4 = reinterpret_cast<const float4*>(g_xt + (size_t)(b*COUT + o) * HWD);
    const int4*   ip4 = reinterpret_cast<const int4*>(idx + b*HWD);
    float4* o4 = reinterpret_cast<float4*>(out + (size_t)(b*COUT + o) * HWD);
    int q0 = cx * 1024 + tid;
    float lsc = sc, lsh = shf;
    #pragma unroll
    for (int it = 0; it < 4; it++) {
        int q = q0 + it*256;
        float4 v = __ldg(xt4 + q);
        int4 kk = __ldg(ip4 + q);
        float4 r;
        r.x = fmaxf(v.x + sAm[kk.x], 0.f) * lsc + lsh;
        r.y = fmaxf(v.y + sAm[kk.y], 0.f) * lsc + lsh;
        r.z = fmaxf(v.z + sAm[kk.z], 0.f) * lsc + lsh;
        r.w = fmaxf(v.w + sAm[kk.w], 0.f) * lsc + lsh;
        o4[q] = r;
    }
}

// ---------------- launch ----------------
extern "C" void kernel_launch(void* const* d_in, const int* in_sizes, int n_in,
                              void* d_out, int out_size) {
    const float* x     = (const float*)d_in[0];
    const int*   idx   = (const int*)  d_in[1];
    const float* Wft   = (const float*)d_in[2];
    const float* Wm    = (const float*)d_in[3];
    const float* gamma = (const float*)d_in[4];
    const float* beta  = (const float*)d_in[5];
    float* out = (float*)d_out;

    k_gemm<<<NGB + 1, 256>>>(x, Wft, Wm);
    k_sums<<<dim3(COUT + 1, BB, NCH), 128>>>(idx);
    k_adj<<<BB*KK, 256>>>();
    k_stats<<<dim3(4, COUT, BB), 256>>>(idx);
    k_out<<<dim3(4, COUT, BB), 256>>>(idx, gamma, beta, out);
}

// round 6
// speedup vs baseline: 1.1544x; 1.1544x over previous
#include <cuda_runtime.h>
#include <cuda_bf16.h>
#include <cstdint>

#define BB 2
#define CIN 128
#define COUT 64
#define KK 64
#define HWD 16384          // 128*128
#define NPIX (BB*HWD)      // 32768
#define GPX 256            // pixels per gemm block
#define NGB (NPIX/GPX)     // 128 gemm blocks

// ---------------- scratch (device globals; no allocation) ----------------
__device__ float g_xt[BB*COUT*HWD];        // xt in [b][o][p] layout (8MB)
__device__ float g_sumsp[BB*KK*COUT*2];    // partial bin sums [b][k][o][z]
__device__ float g_cntp[BB*KK*2];          // partial counts   [b][k][z]
__device__ float g_A[COUT*COUT];           // inv(cov)
__device__ float g_adjmT[BB*KK*COUT];      // adj @ means, TRANSPOSED [b][o][i]
__device__ float g_psum[16*COUT];          // BN partial sums  [(b*8+cx)][o]
__device__ float g_psq[16*COUT];           // BN partial sumsq

// macro params deliberately named to avoid .x/.y/.z/.w member-token capture
#define FMA4(ACC_, XS_, WV_) { (ACC_).x += (XS_)*(WV_).x; (ACC_).y += (XS_)*(WV_).y; (ACC_).z += (XS_)*(WV_).z; (ACC_).w += (XS_)*(WV_).w; }

// ---------------- GEMM halves: xt = x*Wft over 64 channels each ----------------
// chb: channel chunk base (0 or 2); accum!=0: add to existing g_xt and run inverse block
__global__ void __launch_bounds__(512) k_gemm(const float* __restrict__ x,
                                              const float* __restrict__ Wft,
                                              const float* __restrict__ Wm,
                                              int chb, int accum) {
    __shared__ float sbuf[10240];   // gemm: sX 8192 + sW 2048; GJ: 64*133=8512
    __shared__ float prow[128];
    __shared__ float fcol[64];
    const int tid = threadIdx.x;

    if (blockIdx.x == NGB) {
        // ======== cov = Wm Wm^T, Gauss-Jordan inverse (SPD, no pivot) ========
        for (int i = tid; i < 64*64; i += 512) { int r = i >> 6, c = i & 63; sbuf[r*65+c] = Wm[i]; }
        __syncthreads();
        const int i0 = tid & 63, jg = tid >> 6;   // row i0, j-group of 8
        float cv[8];
        #pragma unroll
        for (int jj = 0; jj < 8; jj++) {
            int j = jg*8 + jj;
            float sum = 0.f;
            #pragma unroll 8
            for (int c = 0; c < 64; c++) sum += sbuf[i0*65+c] * sbuf[j*65+c];
            cv[jj] = sum;
        }
        __syncthreads();
        #pragma unroll
        for (int jj = 0; jj < 8; jj++) sbuf[i0*133 + jg*8 + jj] = cv[jj];
        for (int t = tid; t < 64*64; t += 512) { int r = t >> 6, c = t & 63; sbuf[r*133 + 64 + c] = (r == c) ? 1.f : 0.f; }
        const int r = tid & 63, part = tid >> 6;   // row r, 16-col slice
        for (int c = 0; c < 64; c++) {
            __syncthreads();
            if (tid < 128)       prow[tid]     = sbuf[c*133 + tid] * (1.0f / sbuf[c*133 + c]);
            else if (tid < 192)  fcol[tid-128] = sbuf[(tid-128)*133 + c];
            __syncthreads();
            float f = fcol[r];
            if (r == c) {
                for (int j = part*16; j < part*16 + 16; j++) sbuf[r*133 + j] = prow[j];
            } else {
                for (int j = part*16; j < part*16 + 16; j++) sbuf[r*133 + j] -= f * prow[j];
            }
        }
        __syncthreads();
        for (int t = tid; t < 64*64; t += 512) { int rr = t >> 6, cc = t & 63; g_A[t] = sbuf[rr*133 + 64 + cc]; }
        return;
    }

    // ======== GEMM: 256 px x 64 outs; thread tile 4px x 8outs ========
    float4* sX4 = reinterpret_cast<float4*>(sbuf);          // 32 c x 64 quads
    float4* sW4 = reinterpret_cast<float4*>(sbuf + 8192);   // 32 c x 16 f4
    const int GP = blockIdx.x * GPX;
    const int b  = GP >> 14;
    const int P0 = GP & (HWD - 1);
    const int quad = tid & 63;        // pixel quad: px = quad*4..quad*4+3
    const int og   = tid >> 6;        // out group: o = og*8..og*8+7

    float4 a0[4], a1[4];              // a0[p]: outs og*8..+3, a1[p]: og*8+4..+7
    #pragma unroll
    for (int p = 0; p < 4; p++) { a0[p] = make_float4(0.f,0.f,0.f,0.f); a1[p] = make_float4(0.f,0.f,0.f,0.f); }

    for (int ch = chb; ch < chb + 2; ch++) {
        __syncthreads();
        sW4[tid & 511] = __ldg(reinterpret_cast<const float4*>(Wft) + ch*512 + (tid & 511));
        const float* xbase = x + ((size_t)(b*CIN + ch*32)) * HWD + P0;
        #pragma unroll
        for (int t = 0; t < 4; t++) {
            int q = tid + t*512;
            int r = q >> 6, c4 = q & 63;
            sX4[r*64 + c4] = *reinterpret_cast<const float4*>(xbase + (size_t)r * HWD + c4*4);
        }
        __syncthreads();

        #pragma unroll
        for (int cc = 0; cc < 32; cc++) {
            float4 xv = sX4[cc*64 + quad];
            float4 w0 = sW4[cc*16 + og*2];
            float4 w1 = sW4[cc*16 + og*2 + 1];
            FMA4(a0[0], xv.x, w0); FMA4(a1[0], xv.x, w1);
            FMA4(a0[1], xv.y, w0); FMA4(a1[1], xv.y, w1);
            FMA4(a0[2], xv.z, w0); FMA4(a1[2], xv.z, w1);
            FMA4(a0[3], xv.w, w0); FMA4(a1[3], xv.w, w1);
        }
    }

    float* xtb = g_xt + (size_t)b * COUT * HWD + P0 + quad*4;
    float4 v[8];
    v[0] = make_float4(a0[0].x, a0[1].x, a0[2].x, a0[3].x);
    v[1] = make_float4(a0[0].y, a0[1].y, a0[2].y, a0[3].y);
    v[2] = make_float4(a0[0].z, a0[1].z, a0[2].z, a0[3].z);
    v[3] = make_float4(a0[0].w, a0[1].w, a0[2].w, a0[3].w);
    v[4] = make_float4(a1[0].x, a1[1].x, a1[2].x, a1[3].x);
    v[5] = make_float4(a1[0].y, a1[1].y, a1[2].y, a1[3].y);
    v[6] = make_float4(a1[0].z, a1[1].z, a1[2].z, a1[3].z);
    v[7] = make_float4(a1[0].w, a1[1].w, a1[2].w, a1[3].w);
    #pragma unroll
    for (int oo = 0; oo < 8; oo++) {
        float4* ptr = reinterpret_cast<float4*>(xtb + (size_t)(og*8 + oo) * HWD);
        if (accum) {
            float4 pv = *ptr;
            v[oo].x += pv.x; v[oo].y += pv.y; v[oo].z += pv.z; v[oo].w += pv.w;
        }
        *ptr = v[oo];
    }
}

__global__ void k_nop() {}

// ---------------- kernel: per-bin partial sums + counts via shared atomics ----------------
// grid (COUT+1, BB, 2); o==COUT slice computes counts; z = half of pixel plane
__global__ void __launch_bounds__(256) k_sums(const int* __restrict__ idx) {
    __shared__ float sb[64*33];     // bin k, column c: sb[k*33+c]; col=lane -> no intra-warp collisions
    const int tid = threadIdx.x;
    const int o = blockIdx.x, b = blockIdx.y, z = blockIdx.z;
    for (int i = tid; i < 64*33; i += 256) sb[i] = 0.f;
    __syncthreads();
    const int col = tid & 31;
    const int4* ip4 = reinterpret_cast<const int4*>(idx + b*HWD);
    const int q0 = z*2048;
    if (o < COUT) {
        const float4* xt4 = reinterpret_cast<const float4*>(g_xt + (size_t)(b*COUT + o) * HWD);
        #pragma unroll
        for (int it = 0; it < 8; it++) {
            int q = q0 + it*256 + tid;
            float4 v = __ldg(xt4 + q);
            int4 kk = __ldg(ip4 + q);
            atomicAdd(&sb[kk.x*33 + col], v.x);
            atomicAdd(&sb[kk.y*33 + col], v.y);
            atomicAdd(&sb[kk.z*33 + col], v.z);
            atomicAdd(&sb[kk.w*33 + col], v.w);
        }
    } else {
        #pragma unroll
        for (int it = 0; it < 8; it++) {
            int q = q0 + it*256 + tid;
            int4 kk = __ldg(ip4 + q);
            atomicAdd(&sb[kk.x*33 + col], 1.f);
            atomicAdd(&sb[kk.y*33 + col], 1.f);
            atomicAdd(&sb[kk.z*33 + col], 1.f);
            atomicAdd(&sb[kk.w*33 + col], 1.f);
        }
    }
    __syncthreads();
    if (tid < 128) {
        int k = tid >> 1, h = tid & 1;
        float s = 0.f;
        const float* row = sb + k*33 + h*16;
        #pragma unroll
        for (int m = 0; m < 16; m++) s += row[m];
        s += __shfl_xor_sync(0xffffffffu, s, 1);
        if (h == 0) {
            if (o < COUT) g_sumsp[((b*64 + k)*64 + o)*2 + z] = s;
            else          g_cntp[(b*64 + k)*2 + z] = s;
        }
    }
}

// ---------------- kernel: adjacency + adj@means per (b,i) ----------------
__global__ void __launch_bounds__(256) k_adj() {
    __shared__ float sMe[64*65];
    __shared__ float sA[64*64];
    __shared__ float adjrow[64];
    __shared__ float red[256];
    const int tid = threadIdx.x;
    const int b = blockIdx.x >> 6;
    const int i = blockIdx.x & 63;

    for (int t = tid; t < 64*64; t += 256) {
        int k = t >> 6, o = t & 63;
        float2 sp = *reinterpret_cast<const float2*>(g_sumsp + ((size_t)b*4096 + t)*2);
        float sum = sp.x + sp.y;
        float2 cp = *reinterpret_cast<const float2*>(g_cntp + (b*64 + k)*2);
        float cnt = cp.x + cp.y;
        float den = cnt + (cnt == 0.f ? 1.f : 0.f);
        sMe[k*65 + o] = sum / den;
        sA[t] = g_A[t];
    }
    __syncthreads();

    const int j = tid & 63, s = tid >> 6;
    float dreg[64];
    #pragma unroll
    for (int d = 0; d < 64; d++) dreg[d] = sMe[i*65 + d] - sMe[j*65 + d];
    float q = 0.f;
    for (int c = s*16; c < s*16 + 16; c++) {
        float w = 0.f;
        const float4* ar = reinterpret_cast<const float4*>(sA + c*64);
        #pragma unroll
        for (int d4 = 0; d4 < 16; d4++) {
            float4 aa = ar[d4];
            w += aa.x*dreg[4*d4] + aa.y*dreg[4*d4+1] + aa.z*dreg[4*d4+2] + aa.w*dreg[4*d4+3];
        }
        q += dreg[c] * w;
    }
    red[tid] = q;
    __syncthreads();
    if (tid < 64) {
        float qt = red[tid] + red[64 + tid] + red[128 + tid] + red[192 + tid];
        float dist = (tid == i) ? 1e-6f : sqrtf(fmaxf(qt, 1e-12f));
        adjrow[tid] = expf(-dist);
    }
    __syncthreads();
    const int o = tid & 63;
    float part = 0.f;
    for (int jj = s*16; jj < s*16 + 16; jj++) part += adjrow[jj] * sMe[jj*65 + o];
    red[tid] = part;
    __syncthreads();
    if (tid < 64)
        g_adjmT[b*4096 + tid*64 + i] = red[tid] + red[64 + tid] + red[128 + tid] + red[192 + tid];
}

// ---------------- kernel: BN partial statistics ----------------
__global__ void __launch_bounds__(256) k_stats(const int* __restrict__ idx) {
    __shared__ float sAm[64];
    const int tid = threadIdx.x;
    const int cx = blockIdx.x, o = blockIdx.y, b = blockIdx.z;
    if (tid < 64) sAm[tid] = g_adjmT[b*4096 + o*64 + tid];
    __syncthreads();
    const float4* xt4 = reinterpret_cast<const float4*>(g_xt + (size_t)(b*COUT + o) * HWD);
    const int4*   ip4 = reinterpret_cast<const int4*>(idx + b*HWD);
    int q0 = cx * 512 + tid;
    float s = 0.f, sq = 0.f;
    #pragma unroll
    for (int it = 0; it < 2; it++) {
        int q = q0 + it*256;
        float4 v = __ldg(xt4 + q);
        int4 kk = __ldg(ip4 + q);
        float f0 = fmaxf(v.x + sAm[kk.x], 0.f);
        float f1 = fmaxf(v.y + sAm[kk.y], 0.f);
        float f2 = fmaxf(v.z + sAm[kk.z], 0.f);
        float f3 = fmaxf(v.w + sAm[kk.w], 0.f);
        s  += f0 + f1 + f2 + f3;
        sq += f0*f0 + f1*f1 + f2*f2 + f3*f3;
    }
    #pragma unroll
    for (int off = 16; off; off >>= 1) {
        s  += __shfl_down_sync(0xffffffffu, s, off);
        sq += __shfl_down_sync(0xffffffffu, sq, off);
    }
    __shared__ float rs[8], rq[8];
    if ((tid & 31) == 0) { rs[tid >> 5] = s; rq[tid >> 5] = sq; }
    __syncthreads();
    if (tid == 0) {
        float S = 0.f, Q = 0.f;
        #pragma unroll
        for (int w = 0; w < 8; w++) { S += rs[w]; Q += rq[w]; }
        g_psum[(b*8 + cx)*COUT + o] = S;
        g_psq [(b*8 + cx)*COUT + o] = Q;
    }
}

// ---------------- kernel: normalize + write output ----------------
__global__ void __launch_bounds__(256) k_out(const int* __restrict__ idx,
                                             const float* __restrict__ gamma,
                                             const float* __restrict__ beta,
                                             float* __restrict__ out) {
    __shared__ float sAm[64];
    __shared__ float sc, shf;
    const int tid = threadIdx.x;
    const int cx = blockIdx.x, o = blockIdx.y, b = blockIdx.z;
    if (tid < 64) sAm[tid] = g_adjmT[b*4096 + o*64 + tid];
    if (tid == 0) {
        float S = 0.f, Q = 0.f;
        #pragma unroll
        for (int i = 0; i < 16; i++) { S += g_psum[i*COUT + o]; Q += g_psq[i*COUT + o]; }
        const float invN = 1.0f / (float)NPIX;
        float mean = S * invN;
        float var  = Q * invN - mean * mean;
        float inv  = 1.0f / sqrtf(var + 1e-5f);
        float g = __ldg(gamma + o), be = __ldg(beta + o);
        sc  = g * inv;
        shf = be - mean * g * inv;
    }
    __syncthreads();
    const float4* xt4 = reinterpret_cast<const float4*>(g_xt + (size_t)(b*COUT + o) * HWD);
    const int4*   ip4 = reinterpret_cast<const int4*>(idx + b*HWD);
    float4* o4 = reinterpret_cast<float4*>(out + (size_t)(b*COUT + o) * HWD);
    int q0 = cx * 512 + tid;
    float lsc = sc, lsh = shf;
    #pragma unroll
    for (int it = 0; it < 2; it++) {
        int q = q0 + it*256;
        float4 v = __ldg(xt4 + q);
        int4 kk = __ldg(ip4 + q);
        float4 r;
        r.x = fmaxf(v.x + sAm[kk.x], 0.f) * lsc + lsh;
        r.y = fmaxf(v.y + sAm[kk.y], 0.f) * lsc + lsh;
        r.z = fmaxf(v.z + sAm[kk.z], 0.f) * lsc + lsh;
        r.w = fmaxf(v.w + sAm[kk.w], 0.f) * lsc + lsh;
        o4[q] = r;
    }
}

// ---------------- launch ----------------
extern "C" void kernel_launch(void* const* d_in, const int* in_sizes, int n_in,
                              void* d_out, int out_size) {
    const float* x     = (const float*)d_in[0];
    const int*   idx   = (const int*)  d_in[1];
    const float* Wft   = (const float*)d_in[2];
    const float* Wm    = (const float*)d_in[3];
    const float* gamma = (const float*)d_in[4];
    const float* beta  = (const float*)d_in[5];
    float* out = (float*)d_out;

    k_gemm<<<NGB, 512>>>(x, Wft, Wm, 0, 0);       // launch 0: gemmA (abs-8 hypothesis target)
    k_nop<<<1, 32>>>();                            // launch 1
    k_nop<<<1, 32>>>();                            // launch 2
    k_gemm<<<NGB + 1, 512>>>(x, Wft, Wm, 2, 1);   // launch 3: gemmB+inv (pos-3 hypothesis target)
    k_sums<<<dim3(COUT + 1, BB, 2), 256>>>(idx);
    k_adj<<<BB*KK, 256>>>();
    k_stats<<<dim3(8, COUT, BB), 256>>>(idx);
    k_out<<<dim3(8, COUT, BB), 256>>>(idx, gamma, beta, out);
}

// round 7
// speedup vs baseline: 1.3423x; 1.1627x over previous
#include <cuda_runtime.h>
#include <cuda_bf16.h>
#include <cstdint>

#define BB 2
#define CIN 128
#define COUT 64
#define KK 64
#define HWD 16384          // 128*128
#define NPIX (BB*HWD)      // 32768
#define GPX 64             // pixels per gemm block
#define NGB (NPIX/GPX)     // 512 gemm blocks

// ---------------- scratch (device globals; no allocation) ----------------
__device__ float g_xt[BB*COUT*HWD];        // xt in [b][o][p] layout (8MB)
__device__ float g_sumsp[BB*KK*COUT*2];    // partial bin sums [b][k][o][z]
__device__ float g_cntp[BB*KK*2];          // partial counts   [b][k][z]
__device__ float g_A[COUT*COUT];           // inv(cov)
__device__ float g_adjmT[BB*KK*COUT];      // adj @ means, TRANSPOSED [b][o][i]
__device__ float g_psum[16*COUT];          // BN partial sums  [(b*8+cx)][o]
__device__ float g_psq[16*COUT];           // BN partial sumsq

// macro params named to avoid .x/.y/.z/.w member-token capture
#define FMA4(ACC_, XS_, WV_) { (ACC_).x += (XS_)*(WV_).x; (ACC_).y += (XS_)*(WV_).y; (ACC_).z += (XS_)*(WV_).z; (ACC_).w += (XS_)*(WV_).w; }

__global__ void k_nop() {}

// ---------------- GEMM xt = x*Wft (full K) + GJ inverse in extra block ----------------
__global__ void __launch_bounds__(256) k_gemm(const float* __restrict__ x,
                                              const float* __restrict__ Wft,
                                              const float* __restrict__ Wm) {
    __shared__ float sbuf[8576];    // gemm: sX 2048 + sW 2048 floats; GJ: 64*133=8512
    const int tid = threadIdx.x;

    if (blockIdx.x == NGB) {
        // ======== cov = Wm Wm^T, 1-barrier-per-iter Gauss-Jordan (SPD, no pivot) ========
        for (int i = tid; i < 64*64; i += 256) { int r = i >> 6, c = i & 63; sbuf[r*65+c] = Wm[i]; }
        __syncthreads();
        const int i0 = tid & 63, jg = tid >> 6;   // row i0, j-group of 16
        float cv[16];
        #pragma unroll
        for (int jj = 0; jj < 16; jj++) {
            int j = jg*16 + jj;
            float sum = 0.f;
            #pragma unroll 8
            for (int c = 0; c < 64; c++) sum += sbuf[i0*65+c] * sbuf[j*65+c];
            cv[jj] = sum;
        }
        __syncthreads();
        // augmented [cov | I], stride 133 (cov now in regs, safe to overwrite)
        #pragma unroll
        for (int jj = 0; jj < 16; jj++) sbuf[i0*133 + jg*16 + jj] = cv[jj];
        for (int t = tid; t < 64*64; t += 256) { int r = t >> 6, c = t & 63; sbuf[r*133 + 64 + c] = (r == c) ? 1.f : 0.f; }
        // unnormalized elimination: pivot row never modified during its own iter -> 1 barrier/iter
        const int r = tid & 63, part = tid >> 6;   // row r, 32-col slice
        for (int c = 0; c < 64; c++) {
            __syncthreads();
            if (r == c) continue;
            float d = sbuf[c*133 + c];
            float f = sbuf[r*133 + c];
            float t0 = __fdividef(f, d);
            const float* prow = sbuf + c*133 + part*32;
            float* myrow = sbuf + r*133 + part*32;
            #pragma unroll
            for (int j = 0; j < 32; j++) myrow[j] -= t0 * prow[j];
        }
        __syncthreads();
        // normalize on output
        for (int t = tid; t < 64*64; t += 256) {
            int rr = t >> 6, cc = t & 63;
            g_A[t] = __fdividef(sbuf[rr*133 + 64 + cc], sbuf[rr*133 + rr]);
        }
        return;
    }

    // ======== GEMM: 64 px x 64 outs per block; thread tile 4px x 4out ========
    float4* sX4 = reinterpret_cast<float4*>(sbuf);          // [32c][16 quads]
    float4* sW4 = reinterpret_cast<float4*>(sbuf + 2048);   // [32c][16 out-f4]
    const int GP = blockIdx.x * GPX;
    const int b  = GP >> 14;
    const int P0 = GP & (HWD - 1);
    const int quad = tid & 15;        // pixel quad: px = quad*4..+3
    const int og   = tid >> 4;        // out group: o = og*4..+3

    float4 a0 = make_float4(0.f,0.f,0.f,0.f);
    float4 a1 = make_float4(0.f,0.f,0.f,0.f);
    float4 a2 = make_float4(0.f,0.f,0.f,0.f);
    float4 a3 = make_float4(0.f,0.f,0.f,0.f);

    for (int ch = 0; ch < 4; ch++) {
        __syncthreads();
        sW4[tid]       = __ldg(reinterpret_cast<const float4*>(Wft) + ch*512 + tid);
        sW4[tid + 256] = __ldg(reinterpret_cast<const float4*>(Wft) + ch*512 + tid + 256);
        const float* xbase = x + ((size_t)(b*CIN + ch*32)) * HWD + P0;
        {
            int q0 = tid, r0 = q0 >> 4, c0 = q0 & 15;
            sX4[r0*16 + c0] = *reinterpret_cast<const float4*>(xbase + (size_t)r0 * HWD + c0*4);
            int q1 = tid + 256, r1 = q1 >> 4, c1 = q1 & 15;
            sX4[r1*16 + c1] = *reinterpret_cast<const float4*>(xbase + (size_t)r1 * HWD + c1*4);
        }
        __syncthreads();

        #pragma unroll 8
        for (int cc = 0; cc < 32; cc++) {
            float4 xv = sX4[cc*16 + quad];
            float4 wv = sW4[cc*16 + og];
            FMA4(a0, xv.x, wv);
            FMA4(a1, xv.y, wv);
            FMA4(a2, xv.z, wv);
            FMA4(a3, xv.w, wv);
        }
    }

    // epilogue: [b][o][p], coalesced float4 per out row
    float* xtb = g_xt + (size_t)b * COUT * HWD + P0 + quad*4;
    const int ob = og*4;
    *reinterpret_cast<float4*>(xtb + (size_t)(ob+0) * HWD) = make_float4(a0.x, a1.x, a2.x, a3.x);
    *reinterpret_cast<float4*>(xtb + (size_t)(ob+1) * HWD) = make_float4(a0.y, a1.y, a2.y, a3.y);
    *reinterpret_cast<float4*>(xtb + (size_t)(ob+2) * HWD) = make_float4(a0.z, a1.z, a2.z, a3.z);
    *reinterpret_cast<float4*>(xtb + (size_t)(ob+3) * HWD) = make_float4(a0.w, a1.w, a2.w, a3.w);
}

// ---------------- kernel: per-bin partial sums + counts via shared atomics ----------------
// grid (COUT+1, BB, 2); o==COUT slice computes counts; z = half of pixel plane
__global__ void __launch_bounds__(256) k_sums(const int* __restrict__ idx) {
    __shared__ float sb[64*33];     // bin k, column c: sb[k*33+c]; col=lane -> no intra-warp collisions
    const int tid = threadIdx.x;
    const int o = blockIdx.x, b = blockIdx.y, z = blockIdx.z;
    for (int i = tid; i < 64*33; i += 256) sb[i] = 0.f;
    __syncthreads();
    const int col = tid & 31;
    const int4* ip4 = reinterpret_cast<const int4*>(idx + b*HWD);
    const int q0 = z*2048;
    if (o < COUT) {
        const float4* xt4 = reinterpret_cast<const float4*>(g_xt + (size_t)(b*COUT + o) * HWD);
        #pragma unroll
        for (int it = 0; it < 8; it++) {
            int q = q0 + it*256 + tid;
            float4 v = __ldg(xt4 + q);
            int4 kk = __ldg(ip4 + q);
            atomicAdd(&sb[kk.x*33 + col], v.x);
            atomicAdd(&sb[kk.y*33 + col], v.y);
            atomicAdd(&sb[kk.z*33 + col], v.z);
            atomicAdd(&sb[kk.w*33 + col], v.w);
        }
    } else {
        #pragma unroll
        for (int it = 0; it < 8; it++) {
            int q = q0 + it*256 + tid;
            int4 kk = __ldg(ip4 + q);
            atomicAdd(&sb[kk.x*33 + col], 1.f);
            atomicAdd(&sb[kk.y*33 + col], 1.f);
            atomicAdd(&sb[kk.z*33 + col], 1.f);
            atomicAdd(&sb[kk.w*33 + col], 1.f);
        }
    }
    __syncthreads();
    if (tid < 128) {
        int k = tid >> 1, h = tid & 1;
        float s = 0.f;
        const float* row = sb + k*33 + h*16;
        #pragma unroll
        for (int m = 0; m < 16; m++) s += row[m];
        s += __shfl_xor_sync(0xffffffffu, s, 1);
        if (h == 0) {
            if (o < COUT) g_sumsp[((b*64 + k)*64 + o)*2 + z] = s;
            else          g_cntp[(b*64 + k)*2 + z] = s;
        }
    }
}

// ---------------- kernel: adjacency + adj@means per (b,i) ----------------
__global__ void __launch_bounds__(256) k_adj() {
    __shared__ float sMe[64*65];
    __shared__ float sA[64*64];
    __shared__ float adjrow[64];
    __shared__ float red[256];
    const int tid = threadIdx.x;
    const int b = blockIdx.x >> 6;
    const int i = blockIdx.x & 63;

    for (int t = tid; t < 64*64; t += 256) {
        int k = t >> 6, o = t & 63;
        float2 sp = *reinterpret_cast<const float2*>(g_sumsp + ((size_t)b*4096 + t)*2);
        float sum = sp.x + sp.y;
        float2 cp = *reinterpret_cast<const float2*>(g_cntp + (b*64 + k)*2);
        float cnt = cp.x + cp.y;
        float den = cnt + (cnt == 0.f ? 1.f : 0.f);
        sMe[k*65 + o] = sum / den;
        sA[t] = g_A[t];
    }
    __syncthreads();

    const int j = tid & 63, s = tid >> 6;
    float dreg[64];
    #pragma unroll
    for (int d = 0; d < 64; d++) dreg[d] = sMe[i*65 + d] - sMe[j*65 + d];
    float q = 0.f;
    for (int c = s*16; c < s*16 + 16; c++) {
        float w = 0.f;
        const float4* ar = reinterpret_cast<const float4*>(sA + c*64);
        #pragma unroll
        for (int d4 = 0; d4 < 16; d4++) {
            float4 aa = ar[d4];
            w += aa.x*dreg[4*d4] + aa.y*dreg[4*d4+1] + aa.z*dreg[4*d4+2] + aa.w*dreg[4*d4+3];
        }
        q += dreg[c] * w;
    }
    red[tid] = q;
    __syncthreads();
    if (tid < 64) {
        float qt = red[tid] + red[64 + tid] + red[128 + tid] + red[192 + tid];
        float dist = (tid == i) ? 1e-6f : sqrtf(fmaxf(qt, 1e-12f));
        adjrow[tid] = expf(-dist);
    }
    __syncthreads();
    const int o = tid & 63;
    float part = 0.f;
    for (int jj = s*16; jj < s*16 + 16; jj++) part += adjrow[jj] * sMe[jj*65 + o];
    red[tid] = part;
    __syncthreads();
    if (tid < 64)
        g_adjmT[b*4096 + tid*64 + i] = red[tid] + red[64 + tid] + red[128 + tid] + red[192 + tid];
}

// ---------------- kernel: BN partial statistics ----------------
__global__ void __launch_bounds__(256) k_stats(const int* __restrict__ idx) {
    __shared__ float sAm[64];
    const int tid = threadIdx.x;
    const int cx = blockIdx.x, o = blockIdx.y, b = blockIdx.z;
    if (tid < 64) sAm[tid] = g_adjmT[b*4096 + o*64 + tid];
    __syncthreads();
    const float4* xt4 = reinterpret_cast<const float4*>(g_xt + (size_t)(b*COUT + o) * HWD);
    const int4*   ip4 = reinterpret_cast<const int4*>(idx + b*HWD);
    int q0 = cx * 512 + tid;
    float s = 0.f, sq = 0.f;
    #pragma unroll
    for (int it = 0; it < 2; it++) {
        int q = q0 + it*256;
        float4 v = __ldg(xt4 + q);
        int4 kk = __ldg(ip4 + q);
        float f0 = fmaxf(v.x + sAm[kk.x], 0.f);
        float f1 = fmaxf(v.y + sAm[kk.y], 0.f);
        float f2 = fmaxf(v.z + sAm[kk.z], 0.f);
        float f3 = fmaxf(v.w + sAm[kk.w], 0.f);
        s  += f0 + f1 + f2 + f3;
        sq += f0*f0 + f1*f1 + f2*f2 + f3*f3;
    }
    #pragma unroll
    for (int off = 16; off; off >>= 1) {
        s  += __shfl_down_sync(0xffffffffu, s, off);
        sq += __shfl_down_sync(0xffffffffu, sq, off);
    }
    __shared__ float rs[8], rq[8];
    if ((tid & 31) == 0) { rs[tid >> 5] = s; rq[tid >> 5] = sq; }
    __syncthreads();
    if (tid == 0) {
        float S = 0.f, Q = 0.f;
        #pragma unroll
        for (int w = 0; w < 8; w++) { S += rs[w]; Q += rq[w]; }
        g_psum[(b*8 + cx)*COUT + o] = S;
        g_psq [(b*8 + cx)*COUT + o] = Q;
    }
}

// ---------------- kernel: normalize + write output ----------------
__global__ void __launch_bounds__(256) k_out(const int* __restrict__ idx,
                                             const float* __restrict__ gamma,
                                             const float* __restrict__ beta,
                                             float* __restrict__ out) {
    __shared__ float sAm[64];
    __shared__ float sc, shf;
    const int tid = threadIdx.x;
    const int cx = blockIdx.x, o = blockIdx.y, b = blockIdx.z;
    if (tid < 64) sAm[tid] = g_adjmT[b*4096 + o*64 + tid];
    if (tid == 0) {
        float S = 0.f, Q = 0.f;
        #pragma unroll
        for (int i = 0; i < 16; i++) { S += g_psum[i*COUT + o]; Q += g_psq[i*COUT + o]; }
        const float invN = 1.0f / (float)NPIX;
        float mean = S * invN;
        float var  = Q * invN - mean * mean;
        float inv  = 1.0f / sqrtf(var + 1e-5f);
        float g = __ldg(gamma + o), be = __ldg(beta + o);
        sc  = g * inv;
        shf = be - mean * g * inv;
    }
    __syncthreads();
    const float4* xt4 = reinterpret_cast<const float4*>(g_xt + (size_t)(b*COUT + o) * HWD);
    const int4*   ip4 = reinterpret_cast<const int4*>(idx + b*HWD);
    float4* o4 = reinterpret_cast<float4*>(out + (size_t)(b*COUT + o) * HWD);
    int q0 = cx * 512 + tid;
    float lsc = sc, lsh = shf;
    #pragma unroll
    for (int it = 0; it < 2; it++) {
        int q = q0 + it*256;
        float4 v = __ldg(xt4 + q);
        int4 kk = __ldg(ip4 + q);
        float4 r;
        r.x = fmaxf(v.x + sAm[kk.x], 0.f) * lsc + lsh;
        r.y = fmaxf(v.y + sAm[kk.y], 0.f) * lsc + lsh;
        r.z = fmaxf(v.z + sAm[kk.z], 0.f) * lsc + lsh;
        r.w = fmaxf(v.w + sAm[kk.w], 0.f) * lsc + lsh;
        o4[q] = r;
    }
}

// ---------------- launch ----------------
extern "C" void kernel_launch(void* const* d_in, const int* in_sizes, int n_in,
                              void* d_out, int out_size) {
    const float* x     = (const float*)d_in[0];
    const int*   idx   = (const int*)  d_in[1];
    const float* Wft   = (const float*)d_in[2];
    const float* Wm    = (const float*)d_in[3];
    const float* gamma = (const float*)d_in[4];
    const float* beta  = (const float*)d_in[5];
    float* out = (float*)d_out;

    k_nop<<<1, 32>>>();                            // 0
    k_nop<<<1, 32>>>();                            // 1
    k_nop<<<1, 32>>>();                            // 2
    k_gemm<<<NGB + 1, 256>>>(x, Wft, Wm);          // 3 <- profiled next round
    k_sums<<<dim3(COUT + 1, BB, 2), 256>>>(idx);
    k_adj<<<BB*KK, 256>>>();
    k_stats<<<dim3(8, COUT, BB), 256>>>(idx);
    k_out<<<dim3(8, COUT, BB), 256>>>(idx, gamma, beta, out);
}

// round 8
// speedup vs baseline: 1.3478x; 1.0041x over previous
#include <cuda_runtime.h>
#include <cuda_bf16.h>
#include <cstdint>

#define BB 2
#define CIN 128
#define COUT 64
#define KK 64
#define HWD 16384          // 128*128
#define NPIX (BB*HWD)      // 32768
#define GPX 32             // pixels per gemm block
#define NGB (NPIX/GPX)     // 1024 gemm blocks

// ---------------- scratch (device globals; no allocation) ----------------
__device__ float g_xt[BB*COUT*HWD];        // xt in [b][o][p] layout (8MB)
__device__ float g_sumsp[BB*KK*COUT*2];    // partial bin sums [b][k][o][z]
__device__ float g_cntp[BB*KK*2];          // partial counts   [b][k][z]
__device__ float g_A[COUT*COUT];           // inv(cov)
__device__ float g_adjmT[BB*KK*COUT];      // adj @ means, TRANSPOSED [b][o][i]
__device__ float g_psum[16*COUT];          // BN partial sums  [(b*8+cx)][o]
__device__ float g_psq[16*COUT];           // BN partial sumsq

// macro params named to avoid .x/.y/.z/.w member-token capture
#define FMA4(ACC_, XS_, WV_) { (ACC_).x += (XS_)*(WV_).x; (ACC_).y += (XS_)*(WV_).y; (ACC_).z += (XS_)*(WV_).z; (ACC_).w += (XS_)*(WV_).w; }

// ---------------- GEMM xt = x*Wft + packed Gauss-Jordan inverse (block 0) ----------------
__global__ void __launch_bounds__(128) k_gemm(const float* __restrict__ x,
                                              const float* __restrict__ Wft,
                                              const float* __restrict__ Wm) {
    __shared__ __align__(16) float sbuf[4160];   // gemm: sX 1024 + sW 2048; GJ: 64*65 packed aug
    __shared__ float sdiag[64];
    const int tid = threadIdx.x;

    if (blockIdx.x == 0) {
        // ======== packed-slot Gauss-Jordan inverse of cov = Wm Wm^T (SPD, no pivot) ========
        // Phase 1: stage Wm as [64][65]
        for (int i = tid; i < 64*64; i += 128) sbuf[(i >> 6)*65 + (i & 63)] = Wm[i];
        __syncthreads();
        // Phase 2: cov with 4x8 register tile (rows ti*4.., cols tj*8..)
        const int ti = tid & 15;
        const int tj = tid >> 4;
        float acc[4][8];
        #pragma unroll
        for (int p = 0; p < 4; p++)
            #pragma unroll
            for (int q = 0; q < 8; q++) acc[p][q] = 0.f;
        for (int c = 0; c < 64; c++) {
            float ai[4], bj[8];
            #pragma unroll
            for (int p = 0; p < 4; p++) ai[p] = sbuf[(ti*4 + p)*65 + c];
            #pragma unroll
            for (int q = 0; q < 8; q++) bj[q] = sbuf[(tj*8 + q)*65 + c];
            #pragma unroll
            for (int p = 0; p < 4; p++)
                #pragma unroll
                for (int q = 0; q < 8; q++) acc[p][q] += ai[p] * bj[q];
        }
        __syncthreads();   // all Wm reads done; safe to overwrite
        // Phase 3: write M = cov into packed [64][65] (right-identity implicit)
        #pragma unroll
        for (int p = 0; p < 4; p++)
            #pragma unroll
            for (int q = 0; q < 8; q++) sbuf[(ti*4 + p)*65 + tj*8 + q] = acc[p][q];
        // Phase 4: elimination. At iter c: slot c transitions left-col-c -> right-col-c.
        const int r = tid & 63;
        const int half = tid >> 6;      // slots half*32..+31
        float* myrow = sbuf + r*65;
        for (int c = 0; c < 64; c++) {
            __syncthreads();
            if (r == c) {
                if (half == 0) sdiag[c] = sbuf[c*65 + c];
                continue;
            }
            const float* prow = sbuf + c*65;
            float d = prow[c];
            float f = __fdividef(myrow[c], d);
            const int j0 = half*32;
            #pragma unroll
            for (int j = 0; j < 32; j++) {
                int jj = j0 + j;
                float base = myrow[jj];
                if (r == c - 1 && jj == r) base = 1.0f;   // deferred pivot-diag identity
                float val = base - f * prow[jj];
                if (jj == c) val = -f;                    // newborn right-col-c entry
                myrow[jj] = val;
            }
        }
        __syncthreads();
        // Phase 5: normalize rows by saved diag; write inverse
        for (int t = tid; t < 64*64; t += 128) {
            int rr = t >> 6, cc = t & 63;
            float v = sbuf[rr*65 + cc];
            if (rr == 63 && cc == 63) v = 1.0f;           // last pivot's identity never materialized
            g_A[t] = __fdividef(v, sdiag[rr]);
        }
        return;
    }

    // ======== GEMM: 32 px x 64 outs per block; thread tile 4px x 4out ========
    float4* sX4 = reinterpret_cast<float4*>(sbuf);          // [32c][8 quads]
    float4* sW4 = reinterpret_cast<float4*>(sbuf + 1024);   // [32c][16 out-f4]
    const int GP = (blockIdx.x - 1) * GPX;
    const int b  = GP >> 14;
    const int P0 = GP & (HWD - 1);
    const int quad = tid & 7;         // pixel quad: px = quad*4..+3
    const int og   = tid >> 3;        // out group: o = og*4..+3

    float4 a0 = make_float4(0.f,0.f,0.f,0.f);
    float4 a1 = make_float4(0.f,0.f,0.f,0.f);
    float4 a2 = make_float4(0.f,0.f,0.f,0.f);
    float4 a3 = make_float4(0.f,0.f,0.f,0.f);

    for (int ch = 0; ch < 4; ch++) {
        __syncthreads();
        #pragma unroll
        for (int t = 0; t < 4; t++)
            sW4[tid + t*128] = __ldg(reinterpret_cast<const float4*>(Wft) + ch*512 + tid + t*128);
        const float* xbase = x + ((size_t)(b*CIN + ch*32)) * HWD + P0;
        #pragma unroll
        for (int t = 0; t < 2; t++) {
            int q = tid + t*128;
            int r = q >> 3, c4 = q & 7;
            sX4[r*8 + c4] = *reinterpret_cast<const float4*>(xbase + (size_t)r * HWD + c4*4);
        }
        __syncthreads();

        #pragma unroll 8
        for (int cc = 0; cc < 32; cc++) {
            float4 xv = sX4[cc*8 + quad];
            float4 wv = sW4[cc*16 + og];
            FMA4(a0, xv.x, wv);
            FMA4(a1, xv.y, wv);
            FMA4(a2, xv.z, wv);
            FMA4(a3, xv.w, wv);
        }
    }

    // epilogue: [b][o][p], coalesced float4 per out row
    float* xtb = g_xt + (size_t)b * COUT * HWD + P0 + quad*4;
    const int ob = og*4;
    *reinterpret_cast<float4*>(xtb + (size_t)(ob+0) * HWD) = make_float4(a0.x, a1.x, a2.x, a3.x);
    *reinterpret_cast<float4*>(xtb + (size_t)(ob+1) * HWD) = make_float4(a0.y, a1.y, a2.y, a3.y);
    *reinterpret_cast<float4*>(xtb + (size_t)(ob+2) * HWD) = make_float4(a0.z, a1.z, a2.z, a3.z);
    *reinterpret_cast<float4*>(xtb + (size_t)(ob+3) * HWD) = make_float4(a0.w, a1.w, a2.w, a3.w);
}

// ---------------- kernel: per-bin partial sums + counts via shared atomics ----------------
// grid (COUT+1, BB, 2); o==COUT slice computes counts; z = half of pixel plane
__global__ void __launch_bounds__(256) k_sums(const int* __restrict__ idx) {
    __shared__ float sb[64*33];     // bin k, column c: sb[k*33+c]; col=lane -> no intra-warp collisions
    const int tid = threadIdx.x;
    const int o = blockIdx.x, b = blockIdx.y, z = blockIdx.z;
    for (int i = tid; i < 64*33; i += 256) sb[i] = 0.f;
    __syncthreads();
    const int col = tid & 31;
    const int4* ip4 = reinterpret_cast<const int4*>(idx + b*HWD);
    const int q0 = z*2048;
    if (o < COUT) {
        const float4* xt4 = reinterpret_cast<const float4*>(g_xt + (size_t)(b*COUT + o) * HWD);
        #pragma unroll
        for (int it = 0; it < 8; it++) {
            int q = q0 + it*256 + tid;
            float4 v = __ldg(xt4 + q);
            int4 kk = __ldg(ip4 + q);
            atomicAdd(&sb[kk.x*33 + col], v.x);
            atomicAdd(&sb[kk.y*33 + col], v.y);
            atomicAdd(&sb[kk.z*33 + col], v.z);
            atomicAdd(&sb[kk.w*33 + col], v.w);
        }
    } else {
        #pragma unroll
        for (int it = 0; it < 8; it++) {
            int q = q0 + it*256 + tid;
            int4 kk = __ldg(ip4 + q);
            atomicAdd(&sb[kk.x*33 + col], 1.f);
            atomicAdd(&sb[kk.y*33 + col], 1.f);
            atomicAdd(&sb[kk.z*33 + col], 1.f);
            atomicAdd(&sb[kk.w*33 + col], 1.f);
        }
    }
    __syncthreads();
    if (tid < 128) {
        int k = tid >> 1, h = tid & 1;
        float s = 0.f;
        const float* row = sb + k*33 + h*16;
        #pragma unroll
        for (int m = 0; m < 16; m++) s += row[m];
        s += __shfl_xor_sync(0xffffffffu, s, 1);
        if (h == 0) {
            if (o < COUT) g_sumsp[((b*64 + k)*64 + o)*2 + z] = s;
            else          g_cntp[(b*64 + k)*2 + z] = s;
        }
    }
}

// ---------------- kernel: adjacency + adj@means per (b,i) ----------------
__global__ void __launch_bounds__(256) k_adj() {
    __shared__ float sMe[64*65];
    __shared__ float sA[64*64];
    __shared__ float adjrow[64];
    __shared__ float red[256];
    const int tid = threadIdx.x;
    const int b = blockIdx.x >> 6;
    const int i = blockIdx.x & 63;

    for (int t = tid; t < 64*64; t += 256) {
        int k = t >> 6, o = t & 63;
        float2 sp = *reinterpret_cast<const float2*>(g_sumsp + ((size_t)b*4096 + t)*2);
        float sum = sp.x + sp.y;
        float2 cp = *reinterpret_cast<const float2*>(g_cntp + (b*64 + k)*2);
        float cnt = cp.x + cp.y;
        float den = cnt + (cnt == 0.f ? 1.f : 0.f);
        sMe[k*65 + o] = sum / den;
        sA[t] = g_A[t];
    }
    __syncthreads();

    const int j = tid & 63, s = tid >> 6;
    float dreg[64];
    #pragma unroll
    for (int d = 0; d < 64; d++) dreg[d] = sMe[i*65 + d] - sMe[j*65 + d];
    float q = 0.f;
    for (int c = s*16; c < s*16 + 16; c++) {
        float w = 0.f;
        const float4* ar = reinterpret_cast<const float4*>(sA + c*64);
        #pragma unroll
        for (int d4 = 0; d4 < 16; d4++) {
            float4 aa = ar[d4];
            w += aa.x*dreg[4*d4] + aa.y*dreg[4*d4+1] + aa.z*dreg[4*d4+2] + aa.w*dreg[4*d4+3];
        }
        q += dreg[c] * w;
    }
    red[tid] = q;
    __syncthreads();
    if (tid < 64) {
        float qt = red[tid] + red[64 + tid] + red[128 + tid] + red[192 + tid];
        float dist = (tid == i) ? 1e-6f : sqrtf(fmaxf(qt, 1e-12f));
        adjrow[tid] = expf(-dist);
    }
    __syncthreads();
    const int o = tid & 63;
    float part = 0.f;
    for (int jj = s*16; jj < s*16 + 16; jj++) part += adjrow[jj] * sMe[jj*65 + o];
    red[tid] = part;
    __syncthreads();
    if (tid < 64)
        g_adjmT[b*4096 + tid*64 + i] = red[tid] + red[64 + tid] + red[128 + tid] + red[192 + tid];
}

// ---------------- kernel: BN partial statistics ----------------
__global__ void __launch_bounds__(256) k_stats(const int* __restrict__ idx) {
    __shared__ float sAm[64];
    const int tid = threadIdx.x;
    const int cx = blockIdx.x, o = blockIdx.y, b = blockIdx.z;
    if (tid < 64) sAm[tid] = g_adjmT[b*4096 + o*64 + tid];
    __syncthreads();
    const float4* xt4 = reinterpret_cast<const float4*>(g_xt + (size_t)(b*COUT + o) * HWD);
    const int4*   ip4 = reinterpret_cast<const int4*>(idx + b*HWD);
    int q0 = cx * 512 + tid;
    float s = 0.f, sq = 0.f;
    #pragma unroll
    for (int it = 0; it < 2; it++) {
        int q = q0 + it*256;
        float4 v = __ldg(xt4 + q);
        int4 kk = __ldg(ip4 + q);
        float f0 = fmaxf(v.x + sAm[kk.x], 0.f);
        float f1 = fmaxf(v.y + sAm[kk.y], 0.f);
        float f2 = fmaxf(v.z + sAm[kk.z], 0.f);
        float f3 = fmaxf(v.w + sAm[kk.w], 0.f);
        s  += f0 + f1 + f2 + f3;
        sq += f0*f0 + f1*f1 + f2*f2 + f3*f3;
    }
    #pragma unroll
    for (int off = 16; off; off >>= 1) {
        s  += __shfl_down_sync(0xffffffffu, s, off);
        sq += __shfl_down_sync(0xffffffffu, sq, off);
    }
    __shared__ float rs[8], rq[8];
    if ((tid & 31) == 0) { rs[tid >> 5] = s; rq[tid >> 5] = sq; }
    __syncthreads();
    if (tid == 0) {
        float S = 0.f, Q = 0.f;
        #pragma unroll
        for (int w = 0; w < 8; w++) { S += rs[w]; Q += rq[w]; }
        g_psum[(b*8 + cx)*COUT + o] = S;
        g_psq [(b*8 + cx)*COUT + o] = Q;
    }
}

// ---------------- kernel: normalize + write output ----------------
__global__ void __launch_bounds__(256) k_out(const int* __restrict__ idx,
                                             const float* __restrict__ gamma,
                                             const float* __restrict__ beta,
                                             float* __restrict__ out) {
    __shared__ float sAm[64];
    __shared__ float sc, shf;
    const int tid = threadIdx.x;
    const int cx = blockIdx.x, o = blockIdx.y, b = blockIdx.z;
    if (tid < 64) sAm[tid] = g_adjmT[b*4096 + o*64 + tid];
    if (tid == 0) {
        float S = 0.f, Q = 0.f;
        #pragma unroll
        for (int i = 0; i < 16; i++) { S += g_psum[i*COUT + o]; Q += g_psq[i*COUT + o]; }
        const float invN = 1.0f / (float)NPIX;
        float mean = S * invN;
        float var  = Q * invN - mean * mean;
        float inv  = 1.0f / sqrtf(var + 1e-5f);
        float g = __ldg(gamma + o), be = __ldg(beta + o);
        sc  = g * inv;
        shf = be - mean * g * inv;
    }
    __syncthreads();
    const float4* xt4 = reinterpret_cast<const float4*>(g_xt + (size_t)(b*COUT + o) * HWD);
    const int4*   ip4 = reinterpret_cast<const int4*>(idx + b*HWD);
    float4* o4 = reinterpret_cast<float4*>(out + (size_t)(b*COUT + o) * HWD);
    int q0 = cx * 512 + tid;
    float lsc = sc, lsh = shf;
    #pragma unroll
    for (int it = 0; it < 2; it++) {
        int q = q0 + it*256;
        float4 v = __ldg(xt4 + q);
        int4 kk = __ldg(ip4 + q);
        float4 r;
        r.x = fmaxf(v.x + sAm[kk.x], 0.f) * lsc + lsh;
        r.y = fmaxf(v.y + sAm[kk.y], 0.f) * lsc + lsh;
        r.z = fmaxf(v.z + sAm[kk.z], 0.f) * lsc + lsh;
        r.w = fmaxf(v.w + sAm[kk.w], 0.f) * lsc + lsh;
        o4[q] = r;
    }
}

// ---------------- launch ----------------
extern "C" void kernel_launch(void* const* d_in, const int* in_sizes, int n_in,
                              void* d_out, int out_size) {
    const float* x     = (const float*)d_in[0];
    const int*   idx   = (const int*)  d_in[1];
    const float* Wft   = (const float*)d_in[2];
    const float* Wm    = (const float*)d_in[3];
    const float* gamma = (const float*)d_in[4];
    const float* beta  = (const float*)d_in[5];
    float* out = (float*)d_out;

    k_gemm<<<NGB + 1, 128>>>(x, Wft, Wm);
    k_sums<<<dim3(COUT + 1, BB, 2), 256>>>(idx);
    k_adj<<<BB*KK, 256>>>();
    k_stats<<<dim3(8, COUT, BB), 256>>>(idx);
    k_out<<<dim3(8, COUT, BB), 256>>>(idx, gamma, beta, out);
}